// round 1
// baseline (speedup 1.0000x reference)
#include <cuda_runtime.h>
#include <math.h>

#define HH 192
#define WW 448
#define HWSZ (HH*WW)
#define BB 4

// Scratch (allocation-free rule: __device__ globals)
__device__ float g_x[BB*131*HWSZ];   // assembled input to conv chain
__device__ float g_a[BB*128*HWSZ];   // ping
__device__ float g_b[BB*128*HWSZ];   // pong
__device__ float g_d1[BB*25*HWSZ];   // dist after 5x1 conv
__device__ float g_mean[BB*2];

__device__ __forceinline__ float lrelu(float v){ return v >= 0.f ? v : 0.1f*v; }

// ---------------- flow mean over H,W per (b,c) ----------------
__global__ void flow_mean_kernel(const float* __restrict__ flow){
    int bc = blockIdx.x;                 // 0..7
    const float* p = flow + bc*HWSZ;
    float s = 0.f;
    for (int i = threadIdx.x; i < HWSZ; i += 256) s += p[i];
    __shared__ float red[256];
    red[threadIdx.x] = s; __syncthreads();
    for (int o = 128; o > 0; o >>= 1){
        if (threadIdx.x < o) red[threadIdx.x] += red[threadIdx.x+o];
        __syncthreads();
    }
    if (threadIdx.x == 0) g_mean[bc] = red[0] / (float)HWSZ;
}

// ---------------- backwarp diff + centered flow -> g_x ch 0..2 ----------------
__global__ void assemble_kernel(const float* __restrict__ t1,
                                const float* __restrict__ t2,
                                const float* __restrict__ flow){
    int idx = blockIdx.x*256 + threadIdx.x;
    if (idx >= BB*HWSZ) return;
    int b = idx / HWSZ, p = idx % HWSZ;
    int h = p / WW, w = p % WW;
    float f0 = flow[(b*2+0)*HWSZ + p];
    float f1 = flow[(b*2+1)*HWSZ + p];
    float x = (float)w + f0*5.0f;
    float y = (float)h + f1*5.0f;
    float x0f = floorf(x), y0f = floorf(y);
    int x0 = (int)x0f, y0 = (int)y0f;
    float wx1 = x - x0f, wy1 = y - y0f;
    float wx0 = 1.f - wx1, wy0 = 1.f - wy1;
    float d2 = 0.f;
    #pragma unroll
    for (int c = 0; c < 3; c++){
        const float* img = t2 + (b*3+c)*HWSZ;
        float v00 = (y0   >= 0 && y0   < HH && x0   >= 0 && x0   < WW) ? img[y0*WW + x0]       : 0.f;
        float v01 = (y0   >= 0 && y0   < HH && x0+1 >= 0 && x0+1 < WW) ? img[y0*WW + x0+1]     : 0.f;
        float v10 = (y0+1 >= 0 && y0+1 < HH && x0   >= 0 && x0   < WW) ? img[(y0+1)*WW + x0]   : 0.f;
        float v11 = (y0+1 >= 0 && y0+1 < HH && x0+1 >= 0 && x0+1 < WW) ? img[(y0+1)*WW + x0+1] : 0.f;
        float warp = v00*(wy0*wx0) + v01*(wy0*wx1) + v10*(wy1*wx0) + v11*(wy1*wx1);
        float dv = t1[(b*3+c)*HWSZ + p] - warp;
        d2 += dv*dv;
    }
    g_x[(b*131+0)*HWSZ + p] = sqrtf(d2);
    g_x[(b*131+1)*HWSZ + p] = f0 - g_mean[b*2+0];
    g_x[(b*131+2)*HWSZ + p] = f1 - g_mean[b*2+1];
}

// ---------------- feat: 1x1 conv 64->128 + lrelu -> g_x ch 3..130 ----------------
__global__ void __launch_bounds__(256) feat_kernel(const float* __restrict__ fin,
                                                   const float* __restrict__ fw,
                                                   const float* __restrict__ fb){
    int b   = blockIdx.z >> 2;
    int co0 = (blockIdx.z & 3) * 32;
    __shared__ float sw[64][32];
    for (int i = threadIdx.x; i < 64*32; i += 256){
        int ci = i >> 5, co = i & 31;
        sw[ci][co] = fw[(co0+co)*64 + ci];
    }
    __syncthreads();
    int p0 = blockIdx.x*512 + threadIdx.x;
    int p1 = p0 + 256;
    float acc0[32], acc1[32];
    #pragma unroll
    for (int co = 0; co < 32; co++){ acc0[co] = 0.f; acc1[co] = 0.f; }
    const float* base = fin + b*64*HWSZ;
    for (int ci = 0; ci < 64; ci++){
        float v0 = base[ci*HWSZ + p0];
        float v1 = base[ci*HWSZ + p1];
        #pragma unroll
        for (int co = 0; co < 32; co++){
            float wv = sw[ci][co];
            acc0[co] = fmaf(v0, wv, acc0[co]);
            acc1[co] = fmaf(v1, wv, acc1[co]);
        }
    }
    for (int co = 0; co < 32; co++){
        float bv = fb[co0+co];
        g_x[(b*131 + 3 + co0 + co)*HWSZ + p0] = lrelu(acc0[co] + bv);
        g_x[(b*131 + 3 + co0 + co)*HWSZ + p1] = lrelu(acc1[co] + bv);
    }
}

// ---------------- generic 3x3 conv + lrelu ----------------
// block: 256 threads; pixel tile 64x16; 16 Cout per block; thread: 2x2 px x 16 co
template<int UNROLL>
__global__ void __launch_bounds__(256) conv3x3_lrelu_kernel(
        const float* __restrict__ in, int Cin,
        const float* __restrict__ wgt, const float* __restrict__ bias,
        float* __restrict__ out, int Cout){
    const int CO = 16;
    int cogroups = Cout >> 4;
    int b   = blockIdx.z / cogroups;
    int co0 = (blockIdx.z % cogroups) * CO;
    int tile_x = blockIdx.x * 64;
    int tile_y = blockIdx.y * 16;
    int tid = threadIdx.x;
    int tx = tid & 31, ty = tid >> 5;

    __shared__ float s_in[UNROLL][18][66];
    __shared__ float s_w[UNROLL][CO][9];

    float acc[CO][4];
    #pragma unroll
    for (int co = 0; co < CO; co++){
        acc[co][0] = 0.f; acc[co][1] = 0.f; acc[co][2] = 0.f; acc[co][3] = 0.f;
    }

    const float* inb = in + b*Cin*HWSZ;
    for (int c0 = 0; c0 < Cin; c0 += UNROLL){
        int nc = min(UNROLL, Cin - c0);
        for (int i = tid; i < nc*18*66; i += 256){
            int c = i / (18*66); int r = i % (18*66);
            int yy = r / 66, xx = r % 66;
            int gy = tile_y + yy - 1, gx = tile_x + xx - 1;
            float v = 0.f;
            if (gy >= 0 && gy < HH && gx >= 0 && gx < WW)
                v = inb[(c0+c)*HWSZ + gy*WW + gx];
            s_in[c][yy][xx] = v;
        }
        for (int i = tid; i < nc*CO*9; i += 256){
            int c = i / (CO*9); int r = i % (CO*9);
            int co = r / 9, t = r % 9;
            s_w[c][co][t] = wgt[((co0+co)*Cin + c0 + c)*9 + t];
        }
        __syncthreads();
        for (int c = 0; c < nc; c++){
            float iv[4][4];
            #pragma unroll
            for (int dy = 0; dy < 4; dy++)
                #pragma unroll
                for (int dx = 0; dx < 4; dx++)
                    iv[dy][dx] = s_in[c][ty*2+dy][tx*2+dx];
            #pragma unroll
            for (int t = 0; t < 9; t++){
                const int ky = t/3, kx = t%3;
                #pragma unroll
                for (int co = 0; co < CO; co++){
                    float wv = s_w[c][co][t];
                    acc[co][0] = fmaf(iv[ky  ][kx  ], wv, acc[co][0]);
                    acc[co][1] = fmaf(iv[ky  ][kx+1], wv, acc[co][1]);
                    acc[co][2] = fmaf(iv[ky+1][kx  ], wv, acc[co][2]);
                    acc[co][3] = fmaf(iv[ky+1][kx+1], wv, acc[co][3]);
                }
            }
        }
        __syncthreads();
    }
    int y0 = tile_y + ty*2, x0 = tile_x + tx*2;
    #pragma unroll
    for (int co = 0; co < CO; co++){
        float bv = bias[co0+co];
        float* ob = out + (b*Cout + co0 + co)*HWSZ;
        ob[y0*WW + x0]         = lrelu(acc[co][0] + bv);
        ob[y0*WW + x0 + 1]     = lrelu(acc[co][1] + bv);
        ob[(y0+1)*WW + x0]     = lrelu(acc[co][2] + bv);
        ob[(y0+1)*WW + x0 + 1] = lrelu(acc[co][3] + bv);
    }
}

// ---------------- dist1: 5x1 conv 32->25, pad H by 2 ----------------
__global__ void __launch_bounds__(256) dist1_kernel(const float* __restrict__ in,
                                                    const float* __restrict__ w1,
                                                    const float* __restrict__ b1){
    __shared__ float sw[25*32*5];
    for (int i = threadIdx.x; i < 25*32*5; i += 256) sw[i] = w1[i];
    __syncthreads();
    int idx = blockIdx.x*256 + threadIdx.x;
    int b = idx / HWSZ, p = idx % HWSZ;
    int h = p / WW, w = p % WW;
    float acc[25];
    #pragma unroll
    for (int co = 0; co < 25; co++) acc[co] = 0.f;
    const float* inb = in + b*32*HWSZ;
    for (int ci = 0; ci < 32; ci++){
        #pragma unroll
        for (int kh = 0; kh < 5; kh++){
            int gy = h + kh - 2;
            float v = (gy >= 0 && gy < HH) ? inb[ci*HWSZ + gy*WW + w] : 0.f;
            #pragma unroll
            for (int co = 0; co < 25; co++)
                acc[co] = fmaf(v, sw[(co*32+ci)*5 + kh], acc[co]);
        }
    }
    for (int co = 0; co < 25; co++)
        g_d1[(b*25+co)*HWSZ + p] = acc[co] + b1[co];
}

// ---------------- dist2 (1x5) + softmax + unfold-weighted flow avg ----------------
// one block = 224 threads = half a row
__global__ void __launch_bounds__(224) final_kernel(
        const float* __restrict__ w2, const float* __restrict__ b2,
        const float* __restrict__ flow,
        const float* __restrict__ sxw, const float* __restrict__ sxb,
        const float* __restrict__ syw, const float* __restrict__ syb,
        float* __restrict__ out){
    int blk  = blockIdx.x;             // 0 .. B*H*2-1
    int half = blk & 1;
    int bh   = blk >> 1;
    int b = bh / HH, h = bh % HH;
    int x0 = half * 224;

    __shared__ float sd[25][228];
    __shared__ float sw2[25*25*5];
    for (int i = threadIdx.x; i < 25*228; i += 224){
        int ci = i / 228, xx = i % 228;
        int gx = x0 + xx - 2;
        sd[ci][xx] = (gx >= 0 && gx < WW) ? g_d1[(b*25+ci)*HWSZ + h*WW + gx] : 0.f;
    }
    for (int i = threadIdx.x; i < 25*25*5; i += 224) sw2[i] = w2[i];
    __syncthreads();

    int lx = threadIdx.x;
    int x  = x0 + lx;
    float acc[25];
    #pragma unroll
    for (int co = 0; co < 25; co++) acc[co] = 0.f;
    for (int ci = 0; ci < 25; ci++){
        #pragma unroll
        for (int kw = 0; kw < 5; kw++){
            float v = sd[ci][lx + kw];
            #pragma unroll
            for (int co = 0; co < 25; co++)
                acc[co] = fmaf(v, sw2[(co*25+ci)*5 + kw], acc[co]);
        }
    }
    float m = -1e30f;
    #pragma unroll
    for (int co = 0; co < 25; co++){
        float d = acc[co] + b2[co];
        d = -(d*d);
        acc[co] = d;
        m = fmaxf(m, d);
    }
    float s = 0.f;
    #pragma unroll
    for (int co = 0; co < 25; co++){ acc[co] = expf(acc[co] - m); s += acc[co]; }
    float dv = 1.f / s;

    const float* f0 = flow + (b*2+0)*HWSZ;
    const float* f1 = flow + (b*2+1)*HWSZ;
    float sx = sxb[0], sy = syb[0];
    #pragma unroll
    for (int k = 0; k < 25; k++){
        int kh = k / 5, kw = k % 5;
        int gy = h + kh - 2, gx = x + kw - 2;
        float u1 = 0.f, u2 = 0.f;
        if (gy >= 0 && gy < HH && gx >= 0 && gx < WW){
            u1 = f0[gy*WW + gx];
            u2 = f1[gy*WW + gx];
        }
        sx = fmaf(sxw[k], acc[k]*u1, sx);
        sy = fmaf(syw[k], acc[k]*u2, sy);
    }
    out[(b*2+0)*HWSZ + h*WW + x] = sx * dv;
    out[(b*2+1)*HWSZ + h*WW + x] = sy * dv;
}

extern "C" void kernel_launch(void* const* d_in, const int* in_sizes, int n_in,
                              void* d_out, int out_size){
    const float* t1     = (const float*)d_in[0];
    const float* t2     = (const float*)d_in[1];
    const float* ft1    = (const float*)d_in[2];
    // d_in[3] = features_tensor2 (unused by reference)
    const float* flow   = (const float*)d_in[4];
    const float* feat_w = (const float*)d_in[5];
    const float* feat_b = (const float*)d_in[6];
    const float* mw1 = (const float*)d_in[7];  const float* mb1 = (const float*)d_in[8];
    const float* mw2 = (const float*)d_in[9];  const float* mb2 = (const float*)d_in[10];
    const float* mw3 = (const float*)d_in[11]; const float* mb3 = (const float*)d_in[12];
    const float* mw4 = (const float*)d_in[13]; const float* mb4 = (const float*)d_in[14];
    const float* mw5 = (const float*)d_in[15]; const float* mb5 = (const float*)d_in[16];
    const float* mw6 = (const float*)d_in[17]; const float* mb6 = (const float*)d_in[18];
    const float* dw1 = (const float*)d_in[19]; const float* db1 = (const float*)d_in[20];
    const float* dw2 = (const float*)d_in[21]; const float* db2 = (const float*)d_in[22];
    const float* sxw = (const float*)d_in[23]; const float* sxb = (const float*)d_in[24];
    const float* syw = (const float*)d_in[25]; const float* syb = (const float*)d_in[26];
    float* out = (float*)d_out;

    float *px = nullptr, *pa = nullptr, *pb = nullptr;
    cudaGetSymbolAddress((void**)&px, g_x);
    cudaGetSymbolAddress((void**)&pa, g_a);
    cudaGetSymbolAddress((void**)&pb, g_b);

    flow_mean_kernel<<<8, 256>>>(flow);
    assemble_kernel<<<(BB*HWSZ + 255)/256, 256>>>(t1, t2, flow);
    feat_kernel<<<dim3(168, 1, 16), 256>>>(ft1, feat_w, feat_b);

    // conv chain: tiles 7 x 12 over 448x192
    conv3x3_lrelu_kernel<4><<<dim3(7,12,BB*8), 256>>>(px, 131, mw1, mb1, pa, 128);
    conv3x3_lrelu_kernel<4><<<dim3(7,12,BB*8), 256>>>(pa, 128, mw2, mb2, pb, 128);
    conv3x3_lrelu_kernel<4><<<dim3(7,12,BB*4), 256>>>(pb, 128, mw3, mb3, pa, 64);
    conv3x3_lrelu_kernel<4><<<dim3(7,12,BB*4), 256>>>(pa, 64,  mw4, mb4, pb, 64);
    conv3x3_lrelu_kernel<4><<<dim3(7,12,BB*2), 256>>>(pb, 64,  mw5, mb5, pa, 32);
    conv3x3_lrelu_kernel<4><<<dim3(7,12,BB*2), 256>>>(pa, 32,  mw6, mb6, pb, 32);

    dist1_kernel<<<(BB*HWSZ)/256, 256>>>(pb, dw1, db1);
    final_kernel<<<BB*HH*2, 224>>>(dw2, db2, flow, sxw, sxb, syw, syb, out);
}